// round 1
// baseline (speedup 1.0000x reference)
#include <cuda_runtime.h>

// Problem constants (from reference setup_inputs)
constexpr int Bsz  = 64;
constexpr int Nn   = 512;
constexpr int Fdim = 2048;
constexpr int HID  = 1100;
constexpr int NCLS = 512;
constexpr int Pn   = 4;
constexpr int M1   = Bsz * (Nn / Pn);   // 8192 rows after stage-1 pooling
constexpr int M2   = M1 / Pn;           // 2048 rows after stage-2 pooling

// Scratch (no cudaMalloc allowed) — ~109 MB total
__device__ float g_g1[M1 * Fdim];   // node_conv1 output  [8192, 2048]  64 MB
__device__ float g_h [M1 * HID];    // stage-1 activation [8192, 1100]  36 MB
__device__ float g_g2[M2 * HID];    // node_conv2 output  [2048, 1100]   9 MB

// out[r, f] = sum_p x[(4r+p), f] * w[p, f]   (vectorized float4; fd % 4 == 0)
__global__ void node_conv4(const float* __restrict__ x, const float* __restrict__ w,
                           float* __restrict__ out, int rows, int fd) {
    const int f4 = fd >> 2;
    long idx = (long)blockIdx.x * blockDim.x + threadIdx.x;
    long total = (long)rows * f4;
    if (idx >= total) return;
    int r = (int)(idx / f4);
    int j = (int)(idx % f4);
    const float4* x4 = (const float4*)x;
    const float4* w4 = (const float4*)w;
    float4 acc = make_float4(0.f, 0.f, 0.f, 0.f);
#pragma unroll
    for (int p = 0; p < 4; ++p) {
        float4 xv = x4[(long)(4 * r + p) * f4 + j];
        float4 wv = w4[p * f4 + j];
        acc.x = fmaf(xv.x, wv.x, acc.x);
        acc.y = fmaf(xv.y, wv.y, acc.y);
        acc.z = fmaf(xv.z, wv.z, acc.z);
        acc.w = fmaf(xv.w, wv.w, acc.w);
    }
    ((float4*)out)[idx] = acc;
}

// C[M,N] = leaky_relu(A[M,K] @ B[K,N] + bias[N]) ; A,B,C row-major fp32.
// 128x128 block tile, BK=8, 256 threads, 8x8 per-thread microtile.
// Requires M % 128 == 0 (true here: 8192, 2048). N, K arbitrary (guarded).
__global__ __launch_bounds__(256, 2)
void gemm_bias_lrelu(const float* __restrict__ A, const float* __restrict__ Bm,
                     const float* __restrict__ bias, float* __restrict__ C,
                     int M, int Ncols, int K) {
    constexpr int BM = 128, BN = 128, BK = 8;
    __shared__ float As[BK][BM];        // transposed A tile: As[k][m]
    __shared__ float Bs[BK][BN + 4];    // padded

    const int tid = threadIdx.x;
    const int tx = tid & 15;            // 0..15  -> N direction
    const int ty = tid >> 4;            // 0..15  -> M direction
    const int row0 = blockIdx.y * BM;
    const int col0 = blockIdx.x * BN;

    // A tile load map: 128 rows x 8 k, one half-row (4 k) per thread
    const int a_m = tid >> 1;           // 0..127
    const int a_k = (tid & 1) * 4;      // 0 or 4
    // B tile load map: 8 k-rows x 128 cols, 4 cols per thread
    const int b_k = tid >> 5;           // 0..7
    const int b_c = (tid & 31) * 4;     // 0..124

    float acc[8][8] = {};

    const float* Arow = A + (long)(row0 + a_m) * K;

    for (int kt = 0; kt < K; kt += BK) {
#pragma unroll
        for (int i = 0; i < 4; ++i) {
            int k = kt + a_k + i;
            As[a_k + i][a_m] = (k < K) ? Arow[k] : 0.f;
        }
        {
            int kk = kt + b_k;
            const float* Brow = Bm + (long)kk * Ncols;
#pragma unroll
            for (int i = 0; i < 4; ++i) {
                int c = col0 + b_c + i;
                Bs[b_k][b_c + i] = (kk < K && c < Ncols) ? Brow[c] : 0.f;
            }
        }
        __syncthreads();

#pragma unroll
        for (int k = 0; k < BK; ++k) {
            float a[8], b[8];
#pragma unroll
            for (int i = 0; i < 8; ++i) a[i] = As[k][ty * 8 + i];
#pragma unroll
            for (int j = 0; j < 8; ++j) b[j] = Bs[k][tx * 8 + j];
#pragma unroll
            for (int i = 0; i < 8; ++i)
#pragma unroll
                for (int j = 0; j < 8; ++j)
                    acc[i][j] = fmaf(a[i], b[j], acc[i][j]);
        }
        __syncthreads();
    }

#pragma unroll
    for (int i = 0; i < 8; ++i) {
        int r = row0 + ty * 8 + i;
        float* Crow = C + (long)r * Ncols;
#pragma unroll
        for (int j = 0; j < 8; ++j) {
            int c = col0 + tx * 8 + j;
            if (c < Ncols) {
                float v = acc[i][j] + bias[c];
                Crow[c] = (v >= 0.f) ? v : 0.01f * v;
            }
        }
    }
}

extern "C" void kernel_launch(void* const* d_in, const int* in_sizes, int n_in,
                              void* d_out, int out_size) {
    const float* x   = (const float*)d_in[0];
    const float* c1w = (const float*)d_in[1];   // conv1_w [4,2048]
    // d_in[2], d_in[3]: pool1_w/b — dead code (adjacency normalizes to identity)
    const float* p1W = (const float*)d_in[4];   // prop1_W [2048,1100]
    const float* p1B = (const float*)d_in[5];   // prop1_B [1100]
    const float* c2w = (const float*)d_in[6];   // conv2_w [4,1100]
    // d_in[7], d_in[8]: pool2_w/b — dead code
    const float* p2W = (const float*)d_in[9];   // prop2_W [1100,512]
    const float* p2B = (const float*)d_in[10];  // prop2_B [512]
    float* out = (float*)d_out;                 // [64,32,512] = [2048,512]

    float *g1, *h, *g2;
    cudaGetSymbolAddress((void**)&g1, g_g1);
    cudaGetSymbolAddress((void**)&h,  g_h);
    cudaGetSymbolAddress((void**)&g2, g_g2);

    // Stage 1: node_conv1  x[64,512,2048] -> g1[8192,2048]
    {
        long total = (long)M1 * (Fdim / 4);
        int blocks = (int)((total + 255) / 256);
        node_conv4<<<blocks, 256>>>(x, c1w, g1, M1, Fdim);
    }
    // h = leaky_relu(g1 @ prop1_W + prop1_B)   [8192,2048]@[2048,1100]
    {
        dim3 grid((HID + 127) / 128, M1 / 128);
        gemm_bias_lrelu<<<grid, 256>>>(g1, p1W, p1B, h, M1, HID, Fdim);
    }
    // Stage 2: node_conv2  h[8192,1100] -> g2[2048,1100]
    {
        long total = (long)M2 * (HID / 4);
        int blocks = (int)((total + 255) / 256);
        node_conv4<<<blocks, 256>>>(h, c2w, g2, M2, HID);
    }
    // out = leaky_relu(g2 @ prop2_W + prop2_B)   [2048,1100]@[1100,512]
    {
        dim3 grid((NCLS + 127) / 128, M2 / 128);
        gemm_bias_lrelu<<<grid, 256>>>(g2, p2W, p2B, out, M2, NCLS, HID);
    }
}

// round 3
// speedup vs baseline: 5.4968x; 5.4968x over previous
#include <cuda_runtime.h>
#include <cstdint>

// ---------------- problem constants ----------------
constexpr int Fdim = 2048;
constexpr int HID  = 1100;
constexpr int NCLS = 512;
constexpr int M1   = 8192;     // 64 * 512/4
constexpr int M2   = 2048;     // M1 / 4
constexpr int N1PAD = 1152;    // HID padded to mult of 128 (GEMM1 N)
constexpr int K2PAD = 1120;    // HID padded to mult of 32  (GEMM2 K)

// ---------------- scratch (no cudaMalloc allowed) ----------------
__device__ __align__(16) float g_g1 [M1 * Fdim];     // conv1 out (tf32)   64 MB
__device__ __align__(16) float g_h  [M1 * HID];      // stage-1 act        36 MB
__device__ __align__(16) float g_g2 [M2 * K2PAD];    // conv2 out, padded   9 MB
__device__ __align__(16) float g_bt1[N1PAD * Fdim];  // prop1_W^T padded  9.4 MB
__device__ __align__(16) float g_bt2[NCLS * K2PAD];  // prop2_W^T padded  2.3 MB

// ---------------- helpers ----------------
__device__ __forceinline__ uint32_t smem_u32(const void* p) {
    uint32_t a;
    asm("{ .reg .u64 t; cvta.to.shared.u64 t, %1; cvt.u32.u64 %0, t; }" : "=r"(a) : "l"(p));
    return a;
}
__device__ __forceinline__ float tf32r(float x) {
    uint32_t u;
    asm("cvt.rna.tf32.f32 %0, %1;" : "=r"(u) : "f"(x));
    return __uint_as_float(u);
}

#define CP_ASYNC16(saddr, gptr) \
    asm volatile("cp.async.cg.shared.global [%0], [%1], 16;" :: "r"(saddr), "l"(gptr))
#define CP_COMMIT()  asm volatile("cp.async.commit_group;" ::: "memory")
#define CP_WAIT1()   asm volatile("cp.async.wait_group 1;" ::: "memory")
#define CP_WAIT0()   asm volatile("cp.async.wait_group 0;" ::: "memory")

#define LDSM_X4(r, addr) \
    asm volatile("ldmatrix.sync.aligned.m8n8.x4.shared.b16 {%0,%1,%2,%3}, [%4];" \
        : "=r"((r)[0]), "=r"((r)[1]), "=r"((r)[2]), "=r"((r)[3]) : "r"(addr))

#define MMA_TF32(c, a, b0, b1) \
    asm volatile("mma.sync.aligned.m16n8k8.row.col.f32.tf32.tf32.f32 " \
        "{%0,%1,%2,%3}, {%4,%5,%6,%7}, {%8,%9}, {%0,%1,%2,%3};" \
        : "+f"((c)[0]), "+f"((c)[1]), "+f"((c)[2]), "+f"((c)[3]) \
        : "r"((a)[0]), "r"((a)[1]), "r"((a)[2]), "r"((a)[3]), "r"(b0), "r"(b1))

// ---------------- node conv: out[r,:] = sum_p x[4r+p,:] * w[p,:], tf32-rounded, padded ----------------
__global__ void node_conv4(const float* __restrict__ x, const float* __restrict__ w,
                           float* __restrict__ out, int rows, int fd, int ostride) {
    const int f4 = fd >> 2, o4 = ostride >> 2;
    long idx = (long)blockIdx.x * blockDim.x + threadIdx.x;
    if (idx >= (long)rows * o4) return;
    int r = (int)(idx / o4);
    int j = (int)(idx % o4);
    float4 acc = make_float4(0.f, 0.f, 0.f, 0.f);
    if (j < f4) {
        const float4* x4 = (const float4*)x;
        const float4* w4 = (const float4*)w;
#pragma unroll
        for (int p = 0; p < 4; ++p) {
            float4 xv = x4[(long)(4 * r + p) * f4 + j];
            float4 wv = w4[p * f4 + j];
            acc.x = fmaf(xv.x, wv.x, acc.x);
            acc.y = fmaf(xv.y, wv.y, acc.y);
            acc.z = fmaf(xv.z, wv.z, acc.z);
            acc.w = fmaf(xv.w, wv.w, acc.w);
        }
        acc.x = tf32r(acc.x); acc.y = tf32r(acc.y);
        acc.z = tf32r(acc.z); acc.w = tf32r(acc.w);
    }
    ((float4*)out)[idx] = acc;
}

// ---------------- transpose + tf32 round + zero pad:  W[K][N] -> Bt[Npad][Kpad] ----------------
__global__ void transpose_tf32(const float* __restrict__ W, float* __restrict__ Bt,
                               int K, int N, int Kpad, int Npad) {
    __shared__ float t[32][33];
    int k0 = blockIdx.x * 32, n0 = blockIdx.y * 32;
#pragma unroll
    for (int i = 0; i < 4; ++i) {
        int k = k0 + threadIdx.y + i * 8;
        int n = n0 + threadIdx.x;
        t[threadIdx.y + i * 8][threadIdx.x] = (k < K && n < N) ? W[(long)k * N + n] : 0.f;
    }
    __syncthreads();
#pragma unroll
    for (int i = 0; i < 4; ++i) {
        int n = n0 + threadIdx.y + i * 8;
        int k = k0 + threadIdx.x;
        if (n < Npad && k < Kpad)
            Bt[(long)n * Kpad + k] = tf32r(t[threadIdx.x][threadIdx.y + i * 8]);
    }
}

// ---------------- TF32 mma.sync GEMM:  C = leaky_relu(A @ Bt^T + bias) ----------------
// A [M x K] row-major (lda), Bt K-major (ldb), both padded so no K/M guards needed.
// CTA 128x128x32, 256 threads (8 warps as 2 M x 4 N, warp tile 64x32).
// cp.async double buffer, XOR-swizzled smem, ldmatrix fragment loads.
constexpr int GEMM_SMEM = 2 * 2 * 128 * 32 * 4;  // 65536 B (2 stages x (A+B) x 16KB)

__global__ __launch_bounds__(256, 2)
void gemm_tf32_mma(const float* __restrict__ A, const float* __restrict__ Bt,
                   const float* __restrict__ bias, float* __restrict__ C,
                   int Ncols, int lda, int ldb, int ntiles) {
    extern __shared__ float smem[];
    const uint32_t sb = smem_u32(smem);
    const int tid  = threadIdx.x;
    const int lane = tid & 31, warp = tid >> 5;
    const int wm = warp & 1, wn = warp >> 1;
    const int row0 = blockIdx.y * 128;
    const int col0 = blockIdx.x * 128;

    // ---- cp.async maps: 1024 16B chunks per operand tile, 4 per thread ----
    const char* ag[4]; uint32_t asw[4];
    const char* bg[4]; uint32_t bsw[4];
#pragma unroll
    for (int i = 0; i < 4; ++i) {
        int idx = i * 256 + tid;
        int row = idx >> 3, col = idx & 7;
        ag[i]  = (const char*)(A + (size_t)(row0 + row) * lda + col * 4);
        asw[i] = sb + (uint32_t)(row * 128 + ((col ^ (row & 7)) << 4));
        bg[i]  = (const char*)(Bt + (size_t)(col0 + row) * ldb + col * 4);
        bsw[i] = sb + 16384u + (uint32_t)(row * 128 + ((col ^ (row & 7)) << 4));
    }

    // ---- ldmatrix address precompute ----
    // A frags (mfrag i, kstep s): rows wm*64 + i*16 + (lane&7) + ((lane>>3)&1)*8
    uint32_t a_rb[4]; int a_r7[4];
    {
        int rc = wm * 64 + (lane & 7) + (((lane >> 3) & 1) << 3);
#pragma unroll
        for (int i = 0; i < 4; ++i) { int r = rc + i * 16; a_rb[i] = (uint32_t)r << 7; a_r7[i] = r & 7; }
    }
    const int a_hi = lane >> 4;               // chunk half-select
    // B frags (pair j, kstep s): rows wn*32 + j*16 + ((lane>>4)&1)*8 + (lane&7)
    uint32_t b_rb[2]; int b_r7[2];
    {
        int rc = wn * 32 + (((lane >> 4) & 1) << 3) + (lane & 7);
#pragma unroll
        for (int j = 0; j < 2; ++j) { int r = rc + j * 16; b_rb[j] = (uint32_t)r << 7; b_r7[j] = r & 7; }
    }
    const int b_hi = (lane >> 3) & 1;

    float acc[4][4][4] = {};                  // [mfrag][nfrag][reg]

    // ---- prologue: stage 0 ----
#pragma unroll
    for (int i = 0; i < 4; ++i) CP_ASYNC16(asw[i], ag[i]);
#pragma unroll
    for (int i = 0; i < 4; ++i) CP_ASYNC16(bsw[i], bg[i]);
    CP_COMMIT();

    for (int kt = 0; kt < ntiles; ++kt) {
        const uint32_t st = (uint32_t)(kt & 1) * 32768u;
        if (kt + 1 < ntiles) {
            const uint32_t st2 = (uint32_t)((kt + 1) & 1) * 32768u;
            const int koff = (kt + 1) * 128;  // 32 floats per tile step
#pragma unroll
            for (int i = 0; i < 4; ++i) CP_ASYNC16(asw[i] + st2, ag[i] + koff);
#pragma unroll
            for (int i = 0; i < 4; ++i) CP_ASYNC16(bsw[i] + st2, bg[i] + koff);
            CP_COMMIT();
            CP_WAIT1();
        } else {
            CP_WAIT0();
        }
        __syncthreads();

#pragma unroll
        for (int s = 0; s < 4; ++s) {
            uint32_t af[4][4], bf[2][4];
#pragma unroll
            for (int i = 0; i < 4; ++i) {
                uint32_t addr = sb + st + a_rb[i] +
                                ((uint32_t)((2 * s + a_hi) ^ a_r7[i]) << 4);
                LDSM_X4(af[i], addr);
            }
#pragma unroll
            for (int j = 0; j < 2; ++j) {
                uint32_t addr = sb + st + 16384u + b_rb[j] +
                                ((uint32_t)((2 * s + b_hi) ^ b_r7[j]) << 4);
                LDSM_X4(bf[j], addr);
            }
#pragma unroll
            for (int i = 0; i < 4; ++i)
#pragma unroll
                for (int n = 0; n < 4; ++n)
                    MMA_TF32(acc[i][n], af[i], bf[n >> 1][(n & 1) * 2], bf[n >> 1][(n & 1) * 2 + 1]);
        }
        __syncthreads();
    }

    // ---- epilogue: bias + leaky_relu + store (float2, N-col guard) ----
    const int gid = lane >> 2, tig = lane & 3;
#pragma unroll
    for (int i = 0; i < 4; ++i) {
        int r_lo = row0 + wm * 64 + i * 16 + gid;
        int r_hi = r_lo + 8;
#pragma unroll
        for (int n = 0; n < 4; ++n) {
            int c = col0 + wn * 32 + n * 8 + tig * 2;
            if (c < Ncols) {
                float b0 = bias[c], b1 = bias[c + 1];
                float v0 = acc[i][n][0] + b0, v1 = acc[i][n][1] + b1;
                float v2 = acc[i][n][2] + b0, v3 = acc[i][n][3] + b1;
                v0 = (v0 >= 0.f) ? v0 : 0.01f * v0;
                v1 = (v1 >= 0.f) ? v1 : 0.01f * v1;
                v2 = (v2 >= 0.f) ? v2 : 0.01f * v2;
                v3 = (v3 >= 0.f) ? v3 : 0.01f * v3;
                *(float2*)(C + (size_t)r_lo * Ncols + c) = make_float2(v0, v1);
                *(float2*)(C + (size_t)r_hi * Ncols + c) = make_float2(v2, v3);
            }
        }
    }
}

// ---------------- launcher ----------------
extern "C" void kernel_launch(void* const* d_in, const int* in_sizes, int n_in,
                              void* d_out, int out_size) {
    const float* x   = (const float*)d_in[0];
    const float* c1w = (const float*)d_in[1];   // conv1_w [4,2048]
    const float* p1W = (const float*)d_in[4];   // prop1_W [2048,1100]
    const float* p1B = (const float*)d_in[5];   // prop1_B [1100]
    const float* c2w = (const float*)d_in[6];   // conv2_w [4,1100]
    const float* p2W = (const float*)d_in[9];   // prop2_W [1100,512]
    const float* p2B = (const float*)d_in[10];  // prop2_B [512]
    float* out = (float*)d_out;                 // [2048,512]
    // d_in[2,3,7,8]: pool weights — dead code (adjacency normalizes to identity)

    float *g1, *h, *g2, *bt1, *bt2;
    cudaGetSymbolAddress((void**)&g1,  g_g1);
    cudaGetSymbolAddress((void**)&h,   g_h);
    cudaGetSymbolAddress((void**)&g2,  g_g2);
    cudaGetSymbolAddress((void**)&bt1, g_bt1);
    cudaGetSymbolAddress((void**)&bt2, g_bt2);

    cudaFuncSetAttribute(gemm_tf32_mma, cudaFuncAttributeMaxDynamicSharedMemorySize, GEMM_SMEM);

    // weight transposes (K-major, tf32, zero-padded)
    transpose_tf32<<<dim3(Fdim / 32, N1PAD / 32), dim3(32, 8)>>>(p1W, bt1, Fdim, HID, Fdim, N1PAD);
    transpose_tf32<<<dim3(K2PAD / 32, NCLS / 32), dim3(32, 8)>>>(p2W, bt2, HID, NCLS, K2PAD, NCLS);

    // stage 1: conv -> GEMM1 (8192x1100 = 8192x2048 @ 2048x1100)
    {
        long total = (long)M1 * (Fdim / 4);
        node_conv4<<<(int)((total + 255) / 256), 256>>>(x, c1w, g1, M1, Fdim, Fdim);
    }
    gemm_tf32_mma<<<dim3(N1PAD / 128, M1 / 128), 256, GEMM_SMEM>>>(
        g1, bt1, p1B, h, HID, Fdim, Fdim, Fdim / 32);

    // stage 2: conv -> GEMM2 (2048x512 = 2048x1120 @ 1120x512, zero-padded K)
    {
        long total = (long)M2 * (K2PAD / 4);
        node_conv4<<<(int)((total + 255) / 256), 256>>>(h, c2w, g2, M2, HID, K2PAD);
    }
    gemm_tf32_mma<<<dim3(NCLS / 128, M2 / 128), 256, GEMM_SMEM>>>(
        g2, bt2, p2B, out, NCLS, K2PAD, K2PAD, K2PAD / 32);
}

// round 4
// speedup vs baseline: 8.5445x; 1.5544x over previous
#include <cuda_runtime.h>
#include <cuda_bf16.h>
#include <cstdint>

// ---------------- problem constants ----------------
constexpr int Fdim = 2048;
constexpr int HID  = 1100;
constexpr int NCLS = 512;
constexpr int M1   = 8192;     // 64 * 512/4
constexpr int M2   = 2048;     // M1 / 4
constexpr int N1PAD = 1152;    // HID padded to mult of 128 (GEMM1 N)
constexpr int K2PAD = 1152;    // HID padded to mult of 64  (GEMM2 K)

// ---------------- scratch (no cudaMalloc allowed) ----------------
__device__ __align__(16) __nv_bfloat16 g_g1 [M1 * Fdim];     // conv1 out (bf16)  32 MB
__device__ __align__(16) float         g_h  [M1 * HID];      // stage-1 act fp32  36 MB
__device__ __align__(16) __nv_bfloat16 g_g2 [M2 * K2PAD];    // conv2 out, padded 4.7 MB
__device__ __align__(16) __nv_bfloat16 g_bt1[N1PAD * Fdim];  // prop1_W^T bf16    4.7 MB
__device__ __align__(16) __nv_bfloat16 g_bt2[NCLS * K2PAD];  // prop2_W^T bf16    1.2 MB

// ---------------- helpers ----------------
__device__ __forceinline__ uint32_t smem_u32(const void* p) {
    uint32_t a;
    asm("{ .reg .u64 t; cvta.to.shared.u64 t, %1; cvt.u32.u64 %0, t; }" : "=r"(a) : "l"(p));
    return a;
}

#define CP_ASYNC16(saddr, gptr) \
    asm volatile("cp.async.cg.shared.global [%0], [%1], 16;" :: "r"(saddr), "l"(gptr))
#define CP_COMMIT()  asm volatile("cp.async.commit_group;" ::: "memory")
#define CP_WAIT1()   asm volatile("cp.async.wait_group 1;" ::: "memory")
#define CP_WAIT0()   asm volatile("cp.async.wait_group 0;" ::: "memory")

#define LDSM_X4(r, addr) \
    asm volatile("ldmatrix.sync.aligned.m8n8.x4.shared.b16 {%0,%1,%2,%3}, [%4];" \
        : "=r"((r)[0]), "=r"((r)[1]), "=r"((r)[2]), "=r"((r)[3]) : "r"(addr))

#define MMA_BF16(c, a, b0, b1) \
    asm volatile("mma.sync.aligned.m16n8k16.row.col.f32.bf16.bf16.f32 " \
        "{%0,%1,%2,%3}, {%4,%5,%6,%7}, {%8,%9}, {%0,%1,%2,%3};" \
        : "+f"((c)[0]), "+f"((c)[1]), "+f"((c)[2]), "+f"((c)[3]) \
        : "r"((a)[0]), "r"((a)[1]), "r"((a)[2]), "r"((a)[3]), "r"(b0), "r"(b1))

// ---------------- node conv: out[r,:] = bf16(sum_p x[4r+p,:] * w[p,:]), zero-padded ----------------
__global__ void node_conv4_bf16(const float* __restrict__ x, const float* __restrict__ w,
                                __nv_bfloat16* __restrict__ out, int rows, int fd, int ostride) {
    const int f4 = fd >> 2, o4 = ostride >> 2;
    long idx = (long)blockIdx.x * blockDim.x + threadIdx.x;
    if (idx >= (long)rows * o4) return;
    int r = (int)(idx / o4);
    int j = (int)(idx % o4);
    float4 acc = make_float4(0.f, 0.f, 0.f, 0.f);
    if (j < f4) {
        const float4* x4 = (const float4*)x;
        const float4* w4 = (const float4*)w;
#pragma unroll
        for (int p = 0; p < 4; ++p) {
            float4 xv = x4[(long)(4 * r + p) * f4 + j];
            float4 wv = w4[p * f4 + j];
            acc.x = fmaf(xv.x, wv.x, acc.x);
            acc.y = fmaf(xv.y, wv.y, acc.y);
            acc.z = fmaf(xv.z, wv.z, acc.z);
            acc.w = fmaf(xv.w, wv.w, acc.w);
        }
    }
    __nv_bfloat162 lo = __floats2bfloat162_rn(acc.x, acc.y);
    __nv_bfloat162 hi = __floats2bfloat162_rn(acc.z, acc.w);
    uint2 v;
    v.x = *(uint32_t*)&lo;
    v.y = *(uint32_t*)&hi;
    ((uint2*)out)[idx] = v;
}

// ---------------- transpose + bf16 round + zero pad:  W[K][N] -> Bt[Npad][Kpad] ----------------
__global__ void transpose_bf16(const float* __restrict__ W, __nv_bfloat16* __restrict__ Bt,
                               int K, int N, int Kpad, int Npad) {
    __shared__ float t[32][33];
    int k0 = blockIdx.x * 32, n0 = blockIdx.y * 32;
#pragma unroll
    for (int i = 0; i < 4; ++i) {
        int k = k0 + threadIdx.y + i * 8;
        int n = n0 + threadIdx.x;
        t[threadIdx.y + i * 8][threadIdx.x] = (k < K && n < N) ? W[(long)k * N + n] : 0.f;
    }
    __syncthreads();
#pragma unroll
    for (int i = 0; i < 4; ++i) {
        int n = n0 + threadIdx.y + i * 8;
        int k = k0 + threadIdx.x;
        if (n < Npad && k < Kpad)
            Bt[(long)n * Kpad + k] = __float2bfloat16_rn(t[threadIdx.x][threadIdx.y + i * 8]);
    }
}

// ---------------- bf16 mma.sync GEMM:  C = leaky_relu(A @ Bt^T + bias) ----------------
// A [M x K] bf16 row-major (lda), Bt bf16 K-major (ldb), padded: no K/M guards.
// CTA 128x128x64, 256 threads (8 warps as 2 M x 4 N, warp tile 64x32).
// cp.async double buffer, XOR-swizzled 128B smem rows, ldmatrix fragment loads.
constexpr int GEMM_SMEM = 2 * 2 * 128 * 64 * 2;  // 65536 B (2 stages x (A+B) x 16KB)

__global__ __launch_bounds__(256, 2)
void gemm_bf16_mma(const __nv_bfloat16* __restrict__ A, const __nv_bfloat16* __restrict__ Bt,
                   const float* __restrict__ bias, float* __restrict__ C,
                   int Ncols, int lda, int ldb, int ntiles) {
    extern __shared__ char smem[];
    const uint32_t sb = smem_u32(smem);
    const int tid  = threadIdx.x;
    const int lane = tid & 31, warp = tid >> 5;
    const int wm = warp & 1, wn = warp >> 1;
    const int row0 = blockIdx.y * 128;
    const int col0 = blockIdx.x * 128;

    // ---- cp.async maps: tile = 128 rows x 8 chunks(16B), 1024 chunks, 4/thread ----
    const char* ag[4]; uint32_t asw[4];
    const char* bg[4]; uint32_t bsw[4];
#pragma unroll
    for (int i = 0; i < 4; ++i) {
        int idx = i * 256 + tid;
        int row = idx >> 3, col = idx & 7;
        ag[i]  = (const char*)(A + (size_t)(row0 + row) * lda) + col * 16;
        asw[i] = sb + (uint32_t)(row * 128 + ((col ^ (row & 7)) << 4));
        bg[i]  = (const char*)(Bt + (size_t)(col0 + row) * ldb) + col * 16;
        bsw[i] = sb + 16384u + (uint32_t)(row * 128 + ((col ^ (row & 7)) << 4));
    }

    // ---- ldmatrix address precompute ----
    // A frag (mfrag i, kstep s): lane l -> row = wm*64 + i*16 + (l&15), chunk = 2s + (l>>4)
    uint32_t a_rb[4]; int a_r7[4];
    {
        int rc = wm * 64 + (lane & 15);
#pragma unroll
        for (int i = 0; i < 4; ++i) { int r = rc + i * 16; a_rb[i] = (uint32_t)r << 7; a_r7[i] = r & 7; }
    }
    const int a_hi = lane >> 4;
    // B frag (ldm g covers n-groups 2g..2g+1): lane l -> nrow = wn*32 + g*16 + (l>>4)*8 + (l&7),
    // chunk = 2s + ((l>>3)&1)
    uint32_t b_rb[2]; int b_r7[2];
    {
        int rc = wn * 32 + ((lane >> 4) << 3) + (lane & 7);
#pragma unroll
        for (int g = 0; g < 2; ++g) { int r = rc + g * 16; b_rb[g] = (uint32_t)r << 7; b_r7[g] = r & 7; }
    }
    const int b_hi = (lane >> 3) & 1;

    float acc[4][4][4] = {};                  // [mfrag][n8group][reg]

    // ---- prologue: stage 0 ----
#pragma unroll
    for (int i = 0; i < 4; ++i) CP_ASYNC16(asw[i], ag[i]);
#pragma unroll
    for (int i = 0; i < 4; ++i) CP_ASYNC16(bsw[i], bg[i]);
    CP_COMMIT();

    for (int kt = 0; kt < ntiles; ++kt) {
        const uint32_t st = (uint32_t)(kt & 1) * 32768u;
        if (kt + 1 < ntiles) {
            const uint32_t st2 = (uint32_t)((kt + 1) & 1) * 32768u;
            const int koff = (kt + 1) * 128;  // 64 bf16 = 128 B per tile step
#pragma unroll
            for (int i = 0; i < 4; ++i) CP_ASYNC16(asw[i] + st2, ag[i] + koff);
#pragma unroll
            for (int i = 0; i < 4; ++i) CP_ASYNC16(bsw[i] + st2, bg[i] + koff);
            CP_COMMIT();
            CP_WAIT1();
        } else {
            CP_WAIT0();
        }
        __syncthreads();

#pragma unroll
        for (int s = 0; s < 4; ++s) {         // 4 k16 steps per 64-K tile
            uint32_t af[4][4], bf[2][4];
#pragma unroll
            for (int i = 0; i < 4; ++i) {
                uint32_t addr = sb + st + a_rb[i] +
                                ((uint32_t)((2 * s + a_hi) ^ a_r7[i]) << 4);
                LDSM_X4(af[i], addr);
            }
#pragma unroll
            for (int g = 0; g < 2; ++g) {
                uint32_t addr = sb + st + 16384u + b_rb[g] +
                                ((uint32_t)((2 * s + b_hi) ^ b_r7[g]) << 4);
                LDSM_X4(bf[g], addr);
            }
#pragma unroll
            for (int i = 0; i < 4; ++i)
#pragma unroll
                for (int n = 0; n < 4; ++n)
                    MMA_BF16(acc[i][n], af[i], bf[n >> 1][(n & 1) * 2], bf[n >> 1][(n & 1) * 2 + 1]);
        }
        __syncthreads();
    }

    // ---- epilogue: bias + leaky_relu + store (float2, N-col guard) ----
    const int gid = lane >> 2, tig = lane & 3;
#pragma unroll
    for (int i = 0; i < 4; ++i) {
        int r_lo = row0 + wm * 64 + i * 16 + gid;
        int r_hi = r_lo + 8;
#pragma unroll
        for (int n = 0; n < 4; ++n) {
            int c = col0 + wn * 32 + n * 8 + tig * 2;
            if (c < Ncols) {
                float b0 = bias[c], b1 = bias[c + 1];
                float v0 = acc[i][n][0] + b0, v1 = acc[i][n][1] + b1;
                float v2 = acc[i][n][2] + b0, v3 = acc[i][n][3] + b1;
                v0 = (v0 >= 0.f) ? v0 : 0.01f * v0;
                v1 = (v1 >= 0.f) ? v1 : 0.01f * v1;
                v2 = (v2 >= 0.f) ? v2 : 0.01f * v2;
                v3 = (v3 >= 0.f) ? v3 : 0.01f * v3;
                *(float2*)(C + (size_t)r_lo * Ncols + c) = make_float2(v0, v1);
                *(float2*)(C + (size_t)r_hi * Ncols + c) = make_float2(v2, v3);
            }
        }
    }
}

// ---------------- launcher ----------------
extern "C" void kernel_launch(void* const* d_in, const int* in_sizes, int n_in,
                              void* d_out, int out_size) {
    const float* x   = (const float*)d_in[0];
    const float* c1w = (const float*)d_in[1];   // conv1_w [4,2048]
    const float* p1W = (const float*)d_in[4];   // prop1_W [2048,1100]
    const float* p1B = (const float*)d_in[5];   // prop1_B [1100]
    const float* c2w = (const float*)d_in[6];   // conv2_w [4,1100]
    const float* p2W = (const float*)d_in[9];   // prop2_W [1100,512]
    const float* p2B = (const float*)d_in[10];  // prop2_B [512]
    float* out = (float*)d_out;                 // [2048,512]
    // d_in[2,3,7,8]: pool weights — dead code (adjacency normalizes to identity)

    __nv_bfloat16 *g1, *g2, *bt1, *bt2;
    float *h;
    cudaGetSymbolAddress((void**)&g1,  g_g1);
    cudaGetSymbolAddress((void**)&h,   g_h);
    cudaGetSymbolAddress((void**)&g2,  g_g2);
    cudaGetSymbolAddress((void**)&bt1, g_bt1);
    cudaGetSymbolAddress((void**)&bt2, g_bt2);

    cudaFuncSetAttribute(gemm_bf16_mma, cudaFuncAttributeMaxDynamicSharedMemorySize, GEMM_SMEM);

    // weight transposes (K-major, bf16, zero-padded)
    transpose_bf16<<<dim3(Fdim / 32, N1PAD / 32), dim3(32, 8)>>>(p1W, bt1, Fdim, HID, Fdim, N1PAD);
    transpose_bf16<<<dim3(K2PAD / 32, NCLS / 32), dim3(32, 8)>>>(p2W, bt2, HID, NCLS, K2PAD, NCLS);

    // stage 1: conv -> GEMM1 (8192x1100 = 8192x2048 @ 2048x1100)
    {
        long total = (long)M1 * (Fdim / 4);
        node_conv4_bf16<<<(int)((total + 255) / 256), 256>>>(x, c1w, g1, M1, Fdim, Fdim);
    }
    gemm_bf16_mma<<<dim3(N1PAD / 128, M1 / 128), 256, GEMM_SMEM>>>(
        g1, bt1, p1B, h, HID, Fdim, Fdim, Fdim / 64);

    // stage 2: conv -> GEMM2 (2048x512 = 2048x1152 @ 1152x512, zero-padded K)
    {
        long total = (long)M2 * (K2PAD / 4);
        node_conv4_bf16<<<(int)((total + 255) / 256), 256>>>(h, c2w, g2, M2, HID, K2PAD);
    }
    gemm_bf16_mma<<<dim3(NCLS / 128, M2 / 128), 256, GEMM_SMEM>>>(
        g2, bt2, p2B, out, NCLS, K2PAD, K2PAD, K2PAD / 64);
}

// round 5
// speedup vs baseline: 9.0931x; 1.0642x over previous
#include <cuda_runtime.h>
#include <cuda_bf16.h>
#include <cstdint>

// ---------------- problem constants ----------------
constexpr int Fdim = 2048;
constexpr int HID  = 1100;
constexpr int NCLS = 512;
constexpr int M1   = 8192;     // 64 * 512/4
constexpr int M2   = 2048;     // M1 / 4
constexpr int N1PAD = 1152;    // HID padded to mult of 128 (GEMM1 N)
constexpr int K2PAD = 1152;    // = N1PAD; GEMM2 K padding

// ---------------- scratch (no cudaMalloc allowed) ----------------
__device__ __align__(16) __nv_bfloat16 g_g1 [M1 * Fdim];     // conv1 out (bf16)  32 MB
__device__ __align__(16) __nv_bfloat16 g_g2 [M2 * K2PAD];    // fused conv2 out   4.7 MB
__device__ __align__(16) __nv_bfloat16 g_bt1[N1PAD * Fdim];  // prop1_W^T bf16    4.7 MB
__device__ __align__(16) __nv_bfloat16 g_bt2[NCLS * K2PAD];  // prop2_W^T bf16    1.2 MB

// ---------------- helpers ----------------
__device__ __forceinline__ uint32_t smem_u32(const void* p) {
    uint32_t a;
    asm("{ .reg .u64 t; cvta.to.shared.u64 t, %1; cvt.u32.u64 %0, t; }" : "=r"(a) : "l"(p));
    return a;
}

#define CP_ASYNC16(saddr, gptr) \
    asm volatile("cp.async.cg.shared.global [%0], [%1], 16;" :: "r"(saddr), "l"(gptr))
#define CP_COMMIT()  asm volatile("cp.async.commit_group;" ::: "memory")
#define CP_WAIT1()   asm volatile("cp.async.wait_group 1;" ::: "memory")
#define CP_WAIT0()   asm volatile("cp.async.wait_group 0;" ::: "memory")

#define LDSM_X4(r, addr) \
    asm volatile("ldmatrix.sync.aligned.m8n8.x4.shared.b16 {%0,%1,%2,%3}, [%4];" \
        : "=r"((r)[0]), "=r"((r)[1]), "=r"((r)[2]), "=r"((r)[3]) : "r"(addr))

#define MMA_BF16(c, a, b0, b1) \
    asm volatile("mma.sync.aligned.m16n8k16.row.col.f32.bf16.bf16.f32 " \
        "{%0,%1,%2,%3}, {%4,%5,%6,%7}, {%8,%9}, {%0,%1,%2,%3};" \
        : "+f"((c)[0]), "+f"((c)[1]), "+f"((c)[2]), "+f"((c)[3]) \
        : "r"((a)[0]), "r"((a)[1]), "r"((a)[2]), "r"((a)[3]), "r"(b0), "r"(b1))

__device__ __forceinline__ float lrelu(float v) { return (v >= 0.f) ? v : 0.01f * v; }

// ---------------- node conv: out[r,:] = bf16(sum_p x[4r+p,:] * w[p,:]) ----------------
__global__ void node_conv4_bf16(const float* __restrict__ x, const float* __restrict__ w,
                                __nv_bfloat16* __restrict__ out, int rows, int fd) {
    const int f4 = fd >> 2;
    long idx = (long)blockIdx.x * blockDim.x + threadIdx.x;
    if (idx >= (long)rows * f4) return;
    int r = (int)(idx / f4);
    int j = (int)(idx % f4);
    const float4* x4 = (const float4*)x;
    const float4* w4 = (const float4*)w;
    float4 acc = make_float4(0.f, 0.f, 0.f, 0.f);
#pragma unroll
    for (int p = 0; p < 4; ++p) {
        float4 xv = x4[(long)(4 * r + p) * f4 + j];
        float4 wv = w4[p * f4 + j];
        acc.x = fmaf(xv.x, wv.x, acc.x);
        acc.y = fmaf(xv.y, wv.y, acc.y);
        acc.z = fmaf(xv.z, wv.z, acc.z);
        acc.w = fmaf(xv.w, wv.w, acc.w);
    }
    __nv_bfloat162 lo = __floats2bfloat162_rn(acc.x, acc.y);
    __nv_bfloat162 hi = __floats2bfloat162_rn(acc.z, acc.w);
    uint2 v;
    v.x = *(uint32_t*)&lo;
    v.y = *(uint32_t*)&hi;
    ((uint2*)out)[idx] = v;
}

// ---------------- transpose + bf16 round + zero pad:  W[K][N] -> Bt[Npad][Kpad] ----------------
__global__ void transpose_bf16(const float* __restrict__ W, __nv_bfloat16* __restrict__ Bt,
                               int K, int N, int Kpad, int Npad) {
    __shared__ float t[32][33];
    int k0 = blockIdx.x * 32, n0 = blockIdx.y * 32;
#pragma unroll
    for (int i = 0; i < 4; ++i) {
        int k = k0 + threadIdx.y + i * 8;
        int n = n0 + threadIdx.x;
        t[threadIdx.y + i * 8][threadIdx.x] = (k < K && n < N) ? W[(long)k * N + n] : 0.f;
    }
    __syncthreads();
#pragma unroll
    for (int i = 0; i < 4; ++i) {
        int n = n0 + threadIdx.y + i * 8;
        int k = k0 + threadIdx.x;
        if (n < Npad && k < Kpad)
            Bt[(long)n * Kpad + k] = __float2bfloat16_rn(t[threadIdx.x][threadIdx.y + i * 8]);
    }
}

// ---------------- bf16 mma.sync GEMM ----------------
// CTA 128x128x64, 256 threads (8 warps 2Mx4N, warp tile 64x32), 3-stage cp.async.
// FUSE=false: C = leaky_relu(A@Bt^T + bias)  (fp32, N-col guard)
// FUSE=true : g2[r/4, c] = bf16( sum_p w2[p,c] * leaky_relu((A@Bt^T)[4(r/4)+p, c] + bias[c]) )
constexpr int STAGE_BYTES = 32768;               // A 16KB + B 16KB
constexpr int GEMM_SMEM   = 3 * STAGE_BYTES;     // 98304 B

template<bool FUSE>
__global__ __launch_bounds__(256, 2)
void gemm_bf16_mma(const __nv_bfloat16* __restrict__ A, const __nv_bfloat16* __restrict__ Bt,
                   const float* __restrict__ bias, float* __restrict__ C,
                   const float* __restrict__ w2, __nv_bfloat16* __restrict__ g2out,
                   int Ncols, int lda, int ldb, int ntiles, int g2stride) {
    extern __shared__ char smem[];
    const uint32_t sb = smem_u32(smem);
    const int tid  = threadIdx.x;
    const int lane = tid & 31, warp = tid >> 5;
    const int wm = warp & 1, wn = warp >> 1;
    const int row0 = blockIdx.y * 128;
    const int col0 = blockIdx.x * 128;

    // ---- cp.async maps: tile = 128 rows x 8 chunks(16B), 1024 chunks, 4/thread ----
    const char* ag[4]; uint32_t asw[4];
    const char* bg[4]; uint32_t bsw[4];
#pragma unroll
    for (int i = 0; i < 4; ++i) {
        int idx = i * 256 + tid;
        int row = idx >> 3, col = idx & 7;
        ag[i]  = (const char*)(A + (size_t)(row0 + row) * lda) + col * 16;
        asw[i] = sb + (uint32_t)(row * 128 + ((col ^ (row & 7)) << 4));
        bg[i]  = (const char*)(Bt + (size_t)(col0 + row) * ldb) + col * 16;
        bsw[i] = sb + 16384u + (uint32_t)(row * 128 + ((col ^ (row & 7)) << 4));
    }

    // ---- ldmatrix address precompute ----
    uint32_t a_rb[4]; int a_r7[4];
    {
        int rc = wm * 64 + (lane & 15);
#pragma unroll
        for (int i = 0; i < 4; ++i) { int r = rc + i * 16; a_rb[i] = (uint32_t)r << 7; a_r7[i] = r & 7; }
    }
    const int a_hi = lane >> 4;
    uint32_t b_rb[2]; int b_r7[2];
    {
        int rc = wn * 32 + ((lane >> 4) << 3) + (lane & 7);
#pragma unroll
        for (int g = 0; g < 2; ++g) { int r = rc + g * 16; b_rb[g] = (uint32_t)r << 7; b_r7[g] = r & 7; }
    }
    const int b_hi = (lane >> 3) & 1;

    float acc[4][4][4] = {};                  // [mfrag][n8group][reg]

    // ---- prologue: stages 0, 1 ----
#pragma unroll
    for (int s = 0; s < 2; ++s) {
        if (s < ntiles) {
            const uint32_t so = (uint32_t)s * STAGE_BYTES;
            const int koff = s * 128;
#pragma unroll
            for (int i = 0; i < 4; ++i) CP_ASYNC16(asw[i] + so, ag[i] + koff);
#pragma unroll
            for (int i = 0; i < 4; ++i) CP_ASYNC16(bsw[i] + so, bg[i] + koff);
        }
        CP_COMMIT();
    }

    int cur = 0, nxt = 2;
    for (int kt = 0; kt < ntiles; ++kt) {
        if (kt + 1 < ntiles) { CP_WAIT1(); } else { CP_WAIT0(); }
        __syncthreads();

        if (kt + 2 < ntiles) {      // prefetch into the stage just freed
            const uint32_t so = (uint32_t)nxt * STAGE_BYTES;
            const int koff = (kt + 2) * 128;
#pragma unroll
            for (int i = 0; i < 4; ++i) CP_ASYNC16(asw[i] + so, ag[i] + koff);
#pragma unroll
            for (int i = 0; i < 4; ++i) CP_ASYNC16(bsw[i] + so, bg[i] + koff);
            CP_COMMIT();
        }

        const uint32_t st = (uint32_t)cur * STAGE_BYTES;
#pragma unroll
        for (int s = 0; s < 4; ++s) {         // 4 k16 steps per 64-K tile
            uint32_t af[4][4], bf[2][4];
#pragma unroll
            for (int i = 0; i < 4; ++i) {
                uint32_t addr = sb + st + a_rb[i] +
                                ((uint32_t)((2 * s + a_hi) ^ a_r7[i]) << 4);
                LDSM_X4(af[i], addr);
            }
#pragma unroll
            for (int g = 0; g < 2; ++g) {
                uint32_t addr = sb + st + 16384u + b_rb[g] +
                                ((uint32_t)((2 * s + b_hi) ^ b_r7[g]) << 4);
                LDSM_X4(bf[g], addr);
            }
#pragma unroll
            for (int i = 0; i < 4; ++i)
#pragma unroll
                for (int n = 0; n < 4; ++n)
                    MMA_BF16(acc[i][n], af[i], bf[n >> 1][(n & 1) * 2], bf[n >> 1][(n & 1) * 2 + 1]);
        }
        cur = (cur == 2) ? 0 : cur + 1;
        nxt = (nxt == 2) ? 0 : nxt + 1;
    }

    // ---- epilogue ----
    const int gid = lane >> 2, tig = lane & 3;
    if (!FUSE) {
#pragma unroll
        for (int i = 0; i < 4; ++i) {
            int r_lo = row0 + wm * 64 + i * 16 + gid;
            int r_hi = r_lo + 8;
#pragma unroll
            for (int n = 0; n < 4; ++n) {
                int c = col0 + wn * 32 + n * 8 + tig * 2;
                if (c < Ncols) {
                    float b0 = bias[c], b1 = bias[c + 1];
                    float v0 = lrelu(acc[i][n][0] + b0), v1 = lrelu(acc[i][n][1] + b1);
                    float v2 = lrelu(acc[i][n][2] + b0), v3 = lrelu(acc[i][n][3] + b1);
                    *(float2*)(C + (size_t)r_lo * Ncols + c) = make_float2(v0, v1);
                    *(float2*)(C + (size_t)r_hi * Ncols + c) = make_float2(v2, v3);
                }
            }
        }
    } else {
        // fused stage-2 node conv: p = row & 3 = gid & 3; reduce 4 rows via shfl.bfly
        const int p = gid & 3;
        const int grb = (row0 + wm * 64) >> 2;     // group-row base for this warp
#pragma unroll
        for (int i = 0; i < 4; ++i) {
            int gr_lo = grb + i * 4 + (gid >> 2);  // rows r_lo/4 ; r_hi/4 = +2
#pragma unroll
            for (int n = 0; n < 4; ++n) {
                int c = col0 + wn * 32 + n * 8 + tig * 2;
                bool cv = (c < Ncols);
                float b0 = cv ? bias[c] : 0.f,            b1 = cv ? bias[c + 1] : 0.f;
                float w0 = cv ? w2[p * Ncols + c] : 0.f,  w1 = cv ? w2[p * Ncols + c + 1] : 0.f;
                float y0 = lrelu(acc[i][n][0] + b0) * w0;
                float y1 = lrelu(acc[i][n][1] + b1) * w1;
                float y2 = lrelu(acc[i][n][2] + b0) * w0;
                float y3 = lrelu(acc[i][n][3] + b1) * w1;
                y0 += __shfl_xor_sync(0xffffffffu, y0, 4);
                y1 += __shfl_xor_sync(0xffffffffu, y1, 4);
                y2 += __shfl_xor_sync(0xffffffffu, y2, 4);
                y3 += __shfl_xor_sync(0xffffffffu, y3, 4);
                y0 += __shfl_xor_sync(0xffffffffu, y0, 8);
                y1 += __shfl_xor_sync(0xffffffffu, y1, 8);
                y2 += __shfl_xor_sync(0xffffffffu, y2, 8);
                y3 += __shfl_xor_sync(0xffffffffu, y3, 8);
                if ((gid & 3) == 0) {
                    __nv_bfloat162 lo = __floats2bfloat162_rn(y0, y1);
                    __nv_bfloat162 hi = __floats2bfloat162_rn(y2, y3);
                    *(uint32_t*)(g2out + (size_t)gr_lo * g2stride + c)       = *(uint32_t*)&lo;
                    *(uint32_t*)(g2out + (size_t)(gr_lo + 2) * g2stride + c) = *(uint32_t*)&hi;
                }
            }
        }
    }
}

// ---------------- launcher ----------------
extern "C" void kernel_launch(void* const* d_in, const int* in_sizes, int n_in,
                              void* d_out, int out_size) {
    const float* x   = (const float*)d_in[0];
    const float* c1w = (const float*)d_in[1];   // conv1_w [4,2048]
    const float* p1W = (const float*)d_in[4];   // prop1_W [2048,1100]
    const float* p1B = (const float*)d_in[5];   // prop1_B [1100]
    const float* c2w = (const float*)d_in[6];   // conv2_w [4,1100]
    const float* p2W = (const float*)d_in[9];   // prop2_W [1100,512]
    const float* p2B = (const float*)d_in[10];  // prop2_B [512]
    float* out = (float*)d_out;                 // [2048,512]
    // d_in[2,3,7,8]: pool weights — dead code (adjacency normalizes to identity)

    __nv_bfloat16 *g1, *g2, *bt1, *bt2;
    cudaGetSymbolAddress((void**)&g1,  g_g1);
    cudaGetSymbolAddress((void**)&g2,  g_g2);
    cudaGetSymbolAddress((void**)&bt1, g_bt1);
    cudaGetSymbolAddress((void**)&bt2, g_bt2);

    cudaFuncSetAttribute(gemm_bf16_mma<true>,  cudaFuncAttributeMaxDynamicSharedMemorySize, GEMM_SMEM);
    cudaFuncSetAttribute(gemm_bf16_mma<false>, cudaFuncAttributeMaxDynamicSharedMemorySize, GEMM_SMEM);

    // weight transposes (K-major, bf16, zero-padded)
    transpose_bf16<<<dim3(Fdim / 32, N1PAD / 32), dim3(32, 8)>>>(p1W, bt1, Fdim, HID, Fdim, N1PAD);
    transpose_bf16<<<dim3(K2PAD / 32, NCLS / 32), dim3(32, 8)>>>(p2W, bt2, HID, NCLS, K2PAD, NCLS);

    // stage 1: conv1 -> GEMM1 (+ fused conv2) : g2 = conv2(leaky(g1 @ W1 + b1))
    {
        long total = (long)M1 * (Fdim / 4);
        node_conv4_bf16<<<(int)((total + 255) / 256), 256>>>(x, c1w, g1, M1, Fdim);
    }
    gemm_bf16_mma<true><<<dim3(N1PAD / 128, M1 / 128), 256, GEMM_SMEM>>>(
        g1, bt1, p1B, nullptr, c2w, g2, HID, Fdim, Fdim, Fdim / 64, K2PAD);

    // stage 2: GEMM2 (2048x512 = 2048x1152 @ 1152x512, zero-padded K)
    gemm_bf16_mma<false><<<dim3(NCLS / 128, M2 / 128), 256, GEMM_SMEM>>>(
        g2, bt2, p2B, out, nullptr, nullptr, NCLS, K2PAD, K2PAD, K2PAD / 64, 0);
}